// round 10
// baseline (speedup 1.0000x reference)
#include <cuda_runtime.h>
#include <cuda_bf16.h>

// Scratch in device globals (no allocations allowed).
// Both are zero at module load; the finalizing thread resets them to 0
// each run, so every graph replay sees a clean state.
static __device__ double       g_accum;
static __device__ unsigned int g_count;

__global__ void __launch_bounds__(256, 8)
wmse_kernel(const float4* __restrict__ pred4,
            const int4*   __restrict__ lab4,
            const float*  __restrict__ weights,
            float* __restrict__ out,
            long long nv4, long long n) {
    __shared__ float sw[16];
    if (threadIdx.x < 10) sw[threadIdx.x] = weights[threadIdx.x];
    __syncthreads();

    float acc = 0.0f;
    const long long stride = (long long)gridDim.x * blockDim.x;
    for (long long i = (long long)blockIdx.x * blockDim.x + threadIdx.x;
         i < nv4; i += stride) {
        float4 p = pred4[i];
        int4   l = lab4[i];
        float d0 = p.x - (float)l.x;
        float d1 = p.y - (float)l.y;
        float d2 = p.z - (float)l.z;
        float d3 = p.w - (float)l.w;
        acc = fmaf(sw[l.x] * d0, d0, acc);
        acc = fmaf(sw[l.y] * d1, d1, acc);
        acc = fmaf(sw[l.z] * d2, d2, acc);
        acc = fmaf(sw[l.w] * d3, d3, acc);
    }

    // warp reduction
    #pragma unroll
    for (int o = 16; o > 0; o >>= 1)
        acc += __shfl_xor_sync(0xFFFFFFFFu, acc, o);

    __shared__ float warpsum[8];
    int lane = threadIdx.x & 31;
    int wid  = threadIdx.x >> 5;
    if (lane == 0) warpsum[wid] = acc;
    __syncthreads();

    if (wid == 0) {
        float v = (lane < 8) ? warpsum[lane] : 0.0f;
        #pragma unroll
        for (int o = 4; o > 0; o >>= 1)
            v += __shfl_xor_sync(0xFFFFFFFFu, v, o);
        if (lane == 0) {
            // Fire-and-forget accumulate, then signal completion.
            atomicAdd(&g_accum, (double)v);
            __threadfence();   // order my accum-add before my counter-add
            unsigned int done = atomicAdd(&g_count, 1u);
            if (done == gridDim.x - 1) {
                // All blocks' fences have executed: every accum-add is
                // visible. Single-thread finalize — no block-wide wait.
                __threadfence();
                double total = atomicAdd(&g_accum, 0.0);  // atomic read
                *out = (float)(total / (double)n);
                g_accum = 0.0;   // reset for next graph replay
                g_count = 0u;
            }
        }
    }
}

extern "C" void kernel_launch(void* const* d_in, const int* in_sizes, int n_in,
                              void* d_out, int out_size) {
    const float* pred    = (const float*)d_in[0];
    const int*   labels  = (const int*)d_in[1];
    const float* weights = (const float*)d_in[2];
    float* out = (float*)d_out;

    long long n   = (long long)in_sizes[0];
    long long nv4 = n >> 2;   // N = 2^25, divisible by 4

    const int threads = 256;
    int blocks = 148 * 16;  // 2368 blocks — proven fast configuration
    long long needed = (nv4 + threads - 1) / threads;
    if ((long long)blocks > needed) blocks = (int)needed;

    wmse_kernel<<<blocks, threads>>>(
        (const float4*)pred, (const int4*)labels, weights, out, nv4, n);
}